// round 1
// baseline (speedup 1.0000x reference)
#include <cuda_runtime.h>
#include <cstdint>

#define N_ROWS   262144
#define K_CENT   256
#define D_DIM    64
#define ALPHA_F  0.1f
#define NUM_CLS  10

// ---------------- device-global scratch (no allocations allowed) ----------------
__device__ double g_loss;
__device__ int    g_counts[NUM_CLS * NUM_CLS];
__device__ int    g_y_is32;   // 1 if labels are int32-packed, 0 if int64

// ---------------- f32x2 packed helpers (sm_103a) ----------------
__device__ __forceinline__ unsigned long long fma2(unsigned long long a,
                                                   unsigned long long b,
                                                   unsigned long long c) {
    unsigned long long d;
    asm("fma.rn.f32x2 %0, %1, %2, %3;" : "=l"(d) : "l"(a), "l"(b), "l"(c));
    return d;
}
__device__ __forceinline__ unsigned long long add2(unsigned long long a,
                                                   unsigned long long b) {
    unsigned long long d;
    asm("add.rn.f32x2 %0, %1, %2;" : "=l"(d) : "l"(a), "l"(b));
    return d;
}
__device__ __forceinline__ float2 unpack2(unsigned long long a) {
    float2 r;
    asm("mov.b64 {%0, %1}, %2;" : "=f"(r.x), "=f"(r.y) : "l"(a));
    return r;
}

// ---------------- init: zero accumulators + detect label dtype ----------------
__global__ void kmeans_init_kernel(const int* __restrict__ y32) {
    int t = threadIdx.x;
    if (t < NUM_CLS * NUM_CLS) g_counts[t] = 0;
    if (t == 0) { g_loss = 0.0; g_y_is32 = 0; }
    __syncthreads();
    // If labels are int64 (LE), every odd 32-bit word is the high half of a
    // small non-negative value -> 0. If int32, odd words are labels (0..9),
    // and 128 consecutive zeros has probability ~1e-128.
    if (t < 128) {
        if (y32[2 * t + 1] != 0) atomicOr(&g_y_is32, 1);
    }
}

// ---------------- main fused kernel ----------------
extern __shared__ float s_dyn[];  // [K_CENT*D_DIM] centers + [K_CENT] c2

__global__ __launch_bounds__(256, 2)
void kmeans_main_kernel(const float* __restrict__ x,
                        const int*   __restrict__ y32,
                        const float* __restrict__ centers) {
    float* s_c  = s_dyn;                        // 256*64 floats
    float* s_c2 = s_dyn + K_CENT * D_DIM;       // 256 floats
    __shared__ int    s_hist[NUM_CLS * NUM_CLS];
    __shared__ double s_loss;

    const int tid = threadIdx.x;

    // cooperative load of all centers into smem (float4 vectorized)
    {
        const float4* cg = (const float4*)centers;
        float4*       cs = (float4*)s_c;
        #pragma unroll
        for (int i = tid; i < (K_CENT * D_DIM) / 4; i += 256) cs[i] = cg[i];
    }
    if (tid < NUM_CLS * NUM_CLS) s_hist[tid] = 0;
    if (tid == 0) s_loss = 0.0;
    __syncthreads();

    // per-center squared norm (one thread per center)
    {
        const float* cp = s_c + tid * D_DIM;
        float acc = 0.f;
        #pragma unroll
        for (int d0 = 0; d0 < D_DIM; d0++) acc = fmaf(cp[d0], cp[d0], acc);
        s_c2[tid] = acc;
    }
    __syncthreads();

    const int row = blockIdx.x * 256 + tid;

    // load this thread's x row as 16 x 128-bit (pairs packed for f32x2)
    ulonglong2 xv[16];
    {
        const ulonglong2* xg = (const ulonglong2*)(x + (size_t)row * D_DIM);
        #pragma unroll
        for (int j = 0; j < 16; j++) xv[j] = xg[j];
    }

    // x^2 via packed fma
    float x2;
    {
        unsigned long long q0 = 0ull, q1 = 0ull;
        #pragma unroll
        for (int j = 0; j < 16; j++) {
            q0 = fma2(xv[j].x, xv[j].x, q0);
            q1 = fma2(xv[j].y, xv[j].y, q1);
        }
        float2 qq = unpack2(add2(q0, q1));
        x2 = qq.x + qq.y;
    }

    float sw = 0.f, swd = 0.f;
    float dmin = 3.4e38f;
    int   kbest = 0;

    for (int k = 0; k < K_CENT; k++) {
        const ulonglong2* cp = (const ulonglong2*)(s_c + (k << 6));
        unsigned long long a0 = 0ull, a1 = 0ull, a2 = 0ull, a3 = 0ull;
        #pragma unroll
        for (int j = 0; j < 16; j += 2) {
            ulonglong2 c0 = cp[j];
            ulonglong2 c1 = cp[j + 1];
            a0 = fma2(xv[j].x,     c0.x, a0);
            a1 = fma2(xv[j].y,     c0.y, a1);
            a2 = fma2(xv[j + 1].x, c1.x, a2);
            a3 = fma2(xv[j + 1].y, c1.y, a3);
        }
        float2 s2  = unpack2(add2(add2(a0, a1), add2(a2, a3)));
        float  dot = s2.x + s2.y;
        float  d   = fmaf(-2.f, dot, x2 + s_c2[k]);
        d = fmaxf(d, 0.f);

        // w = (1+d)^(-0.1) = exp2(-0.1 * log2(1+d)); 2 MUFU ops
        float w = __powf(1.f + d, -ALPHA_F);
        sw  += w;
        swd  = fmaf(w, d, swd);

        if (d < dmin) { dmin = d; kbest = k; }
    }

    // per-row loss, warp-reduced then block double accumulate
    float row_loss = swd / sw;
    #pragma unroll
    for (int off = 16; off > 0; off >>= 1)
        row_loss += __shfl_xor_sync(0xFFFFFFFFu, row_loss, off);
    if ((tid & 31) == 0) atomicAdd_block(&s_loss, (double)row_loss);

    // histogram contribution (only clusters 0..9 matter)
    if (kbest < NUM_CLS) {
        int lab = g_y_is32 ? y32[row] : y32[2 * row];
        atomicAdd_block(&s_hist[kbest * NUM_CLS + lab], 1);
    }
    __syncthreads();

    if (tid == 0) atomicAdd(&g_loss, s_loss);
    if (tid < NUM_CLS * NUM_CLS && s_hist[tid] > 0)
        atomicAdd(&g_counts[tid], s_hist[tid]);
}

// ---------------- finalize: greedy label matching (exact reference semantics) --
__global__ void kmeans_finalize_kernel(float* __restrict__ out) {
    if (threadIdx.x != 0 || blockIdx.x != 0) return;

    float counts[NUM_CLS * NUM_CLS];
    #pragma unroll
    for (int i = 0; i < NUM_CLS * NUM_CLS; i++) counts[i] = (float)g_counts[i];

    bool  used[NUM_CLS];
    #pragma unroll
    for (int i = 0; i < NUM_CLS; i++) used[i] = false;

    float correct = 0.f;
    for (int i = 0; i < NUM_CLS; i++) {
        const float* bin = &counts[i * NUM_CLS];
        float tot = 0.f;
        for (int j = 0; j < NUM_CLS; j++) tot += bin[j];

        // first-max argmax (matches jnp.argmax tie behavior)
        int   label = 0;
        float best  = bin[0];
        for (int j = 1; j < NUM_CLS; j++)
            if (bin[j] > best) { best = bin[j]; label = j; }

        if (used[label]) {
            // re-pick with used labels masked to 0 (single-level, like reference)
            int   l2 = 0;
            float b2 = used[0] ? 0.f : bin[0];
            for (int j = 1; j < NUM_CLS; j++) {
                float v = used[j] ? 0.f : bin[j];
                if (v > b2) { b2 = v; l2 = j; }
            }
            label = l2;
        }
        if (tot > 0.f) {
            correct += bin[label];
            used[label] = true;
        }
    }

    out[0] = (float)g_loss;
    out[1] = correct / (float)N_ROWS;
}

// ---------------- launch ----------------
extern "C" void kernel_launch(void* const* d_in, const int* in_sizes, int n_in,
                              void* d_out, int out_size) {
    const float* x       = (const float*)d_in[0];
    const int*   y32     = (const int*)d_in[1];   // int32 or int64 (auto-detected)
    const float* centers = (const float*)d_in[2];

    const size_t smem = (size_t)(K_CENT * D_DIM + K_CENT) * sizeof(float);
    cudaFuncSetAttribute(kmeans_main_kernel,
                         cudaFuncAttributeMaxDynamicSharedMemorySize, (int)smem);

    kmeans_init_kernel<<<1, 128>>>(y32);
    kmeans_main_kernel<<<N_ROWS / 256, 256, smem>>>(x, y32, centers);
    kmeans_finalize_kernel<<<1, 1>>>((float*)d_out);
}

// round 3
// speedup vs baseline: 1.7559x; 1.7559x over previous
#include <cuda_runtime.h>
#include <cuda_bf16.h>
#include <cstdint>
#include <cfloat>

#define N_ROWS   262144
#define K_CENT   256
#define D_DIM    64
#define NUM_CLS  10
#define TILE_M   128
#define N_TILES  (N_ROWS / TILE_M)   /* 2048 */
#define GRID_X   296
#define NTHREADS 256

// ---------------- device-global scratch ----------------
__device__ double g_loss;
__device__ int    g_counts[NUM_CLS * NUM_CLS];
__device__ int    g_y_is32;

// ---------------- helpers ----------------
// split float pair into round-to-nearest bf16 hi pair + bf16 lo (residual) pair
__device__ __forceinline__ void split2(float a, float b, uint32_t& hi, uint32_t& lo) {
    __nv_bfloat162 h = __floats2bfloat162_rn(a, b);
    float la = a - __bfloat162float(h.x);
    float lb = b - __bfloat162float(h.y);
    __nv_bfloat162 l = __floats2bfloat162_rn(la, lb);
    hi = *reinterpret_cast<uint32_t*>(&h);
    lo = *reinterpret_cast<uint32_t*>(&l);
}

// mma.sync m16n8k16 bf16 -> f32 accumulate (baseline PTX, no 'a' feature needed)
__device__ __forceinline__ void mma_bf16(float& d0, float& d1, float& d2, float& d3,
                                         uint32_t a0, uint32_t a1, uint32_t a2, uint32_t a3,
                                         uint32_t b0, uint32_t b1) {
    asm("mma.sync.aligned.m16n8k16.row.col.f32.bf16.bf16.f32 "
        "{%0,%1,%2,%3}, {%4,%5,%6,%7}, {%8,%9}, {%0,%1,%2,%3};"
        : "+f"(d0), "+f"(d1), "+f"(d2), "+f"(d3)
        : "r"(a0), "r"(a1), "r"(a2), "r"(a3), "r"(b0), "r"(b1));
}

// ---------------- init: zero accumulators + detect label dtype ----------------
__global__ void kmeans_init_kernel(const int* __restrict__ y32) {
    int t = threadIdx.x;
    if (t < NUM_CLS * NUM_CLS) g_counts[t] = 0;
    if (t == 0) { g_loss = 0.0; g_y_is32 = 0; }
    __syncthreads();
    if (t < 128) {
        if (y32[2 * t + 1] != 0) atomicOr(&g_y_is32, 1);
    }
}

// dynamic smem layout:
//   uint4 B[256*16]  : per (n, kc, t4) one 16B unit {hi_b0, hi_b1, lo_b0, lo_b1},
//                      unit idx u = (kc*4+t4) ^ ((n&1)<<2)  (conflict-free LDS.128)
//   float c2[256]
struct SmemLayout {
    uint4 B[K_CENT * 16];
    float c2[K_CENT];
};

__global__ __launch_bounds__(NTHREADS, 2)
void kmeans_hmma_kernel(const float* __restrict__ x,
                        const int*   __restrict__ y32,
                        const float* __restrict__ centers) {
    extern __shared__ unsigned char s_raw[];
    SmemLayout* sm = reinterpret_cast<SmemLayout*>(s_raw);
    __shared__ int    s_hist[NUM_CLS * NUM_CLS];
    __shared__ double s_loss;

    const int tid  = threadIdx.x;
    const int wid  = tid >> 5;
    const int lane = tid & 31;
    const int g    = lane >> 2;   // row group within mma tile (0..7)
    const int t4   = lane & 3;

    if (tid < NUM_CLS * NUM_CLS) s_hist[tid] = 0;
    if (tid == 0) s_loss = 0.0;

    // ---- build B fragments (centers hi/lo) in smem, once per CTA ----
    for (int w = tid; w < K_CENT * 16; w += NTHREADS) {
        int n  = w >> 4;
        int u16 = w & 15;
        int kc = u16 >> 2, tt = u16 & 3;
        int kb = kc * 16 + tt * 2;
        const float* cn = centers + n * D_DIM;
        float2 pa = *(const float2*)(cn + kb);
        float2 pb = *(const float2*)(cn + kb + 8);
        uint32_t hi0, lo0, hi1, lo1;
        split2(pa.x, pa.y, hi0, lo0);
        split2(pb.x, pb.y, hi1, lo1);
        int u = u16 ^ ((n & 1) << 2);
        sm->B[n * 16 + u] = make_uint4(hi0, hi1, lo0, lo1);
    }
    // center norms (fp32 exact)
    if (tid < K_CENT) {
        const float4* cp = (const float4*)(centers + tid * D_DIM);
        float a = 0.f;
        #pragma unroll
        for (int j = 0; j < 16; j++) {
            float4 v = cp[j];
            a = fmaf(v.x, v.x, a); a = fmaf(v.y, v.y, a);
            a = fmaf(v.z, v.z, a); a = fmaf(v.w, v.w, a);
        }
        sm->c2[tid] = a;
    }
    __syncthreads();
    const int y_is32 = g_y_is32;

    // per-thread B base: n = ng*8 + g, n&1 == g&1 (ng*8 is even)
    const uint4* Bbase = sm->B + g * 16;
    const int    uswz  = (g & 1) << 2;

    float loss_local = 0.f;

    for (int t = blockIdx.x; t < N_TILES; t += GRID_X) {
        const int r0 = t * TILE_M + wid * 16 + g;   // this thread's row pair: r0, r0+8
        const float* xr0 = x + (size_t)r0 * D_DIM;
        const float* xr1 = xr0 + 8 * D_DIM;

        // ---- A fragments from gmem (hi/lo), plus row-norm partials ----
        uint32_t ahi[4][4], alo[4][4];
        float x2a = 0.f, x2b = 0.f;
        #pragma unroll
        for (int kc = 0; kc < 4; kc++) {
            int cb = kc * 16 + t4 * 2;
            float2 p00 = *(const float2*)(xr0 + cb);
            float2 p01 = *(const float2*)(xr0 + cb + 8);
            float2 p10 = *(const float2*)(xr1 + cb);
            float2 p11 = *(const float2*)(xr1 + cb + 8);
            x2a = fmaf(p00.x, p00.x, x2a); x2a = fmaf(p00.y, p00.y, x2a);
            x2a = fmaf(p01.x, p01.x, x2a); x2a = fmaf(p01.y, p01.y, x2a);
            x2b = fmaf(p10.x, p10.x, x2b); x2b = fmaf(p10.y, p10.y, x2b);
            x2b = fmaf(p11.x, p11.x, x2b); x2b = fmaf(p11.y, p11.y, x2b);
            split2(p00.x, p00.y, ahi[kc][0], alo[kc][0]);
            split2(p10.x, p10.y, ahi[kc][1], alo[kc][1]);
            split2(p01.x, p01.y, ahi[kc][2], alo[kc][2]);
            split2(p11.x, p11.y, ahi[kc][3], alo[kc][3]);
        }
        // complete row norms across the quad (each lane holds 16 of 64 elems/row)
        x2a += __shfl_xor_sync(0xFFFFFFFFu, x2a, 1);
        x2a += __shfl_xor_sync(0xFFFFFFFFu, x2a, 2);
        x2b += __shfl_xor_sync(0xFFFFFFFFu, x2b, 1);
        x2b += __shfl_xor_sync(0xFFFFFFFFu, x2b, 2);

        float sw0 = 0.f, swd0 = 0.f, sw1 = 0.f, swd1 = 0.f;
        float dmin0 = FLT_MAX, dmin1 = FLT_MAX;
        int   k0 = 0, k1 = 0;

        #pragma unroll 2
        for (int ng = 0; ng < 32; ng++) {
            float2 c2p = *(const float2*)(sm->c2 + ng * 8 + t4 * 2);
            float acc0 = 0.f, acc1 = 0.f, acc2 = 0.f, acc3 = 0.f;
            const uint4* Bn = Bbase + ng * 128;   // +ng*8 rows * 16 units
            #pragma unroll
            for (int kc = 0; kc < 4; kc++) {
                uint4 bv = Bn[(kc * 4 + t4) ^ uswz];
                mma_bf16(acc0, acc1, acc2, acc3,
                         ahi[kc][0], ahi[kc][1], ahi[kc][2], ahi[kc][3], bv.x, bv.y);
                mma_bf16(acc0, acc1, acc2, acc3,
                         ahi[kc][0], ahi[kc][1], ahi[kc][2], ahi[kc][3], bv.z, bv.w);
                mma_bf16(acc0, acc1, acc2, acc3,
                         alo[kc][0], alo[kc][1], alo[kc][2], alo[kc][3], bv.x, bv.y);
            }
            // fused epilogue for this 8-col group
            const int cb = ng * 8 + t4 * 2;
            float pre0 = x2a + c2p.x, pre1 = x2a + c2p.y;
            float pre2 = x2b + c2p.x, pre3 = x2b + c2p.y;
            float d00 = fmaxf(fmaf(-2.f, acc0, pre0), 0.f);
            float d01 = fmaxf(fmaf(-2.f, acc1, pre1), 0.f);
            float d10 = fmaxf(fmaf(-2.f, acc2, pre2), 0.f);
            float d11 = fmaxf(fmaf(-2.f, acc3, pre3), 0.f);
            float w00 = __powf(1.f + d00, -0.1f);
            float w01 = __powf(1.f + d01, -0.1f);
            float w10 = __powf(1.f + d10, -0.1f);
            float w11 = __powf(1.f + d11, -0.1f);
            sw0 += w00 + w01;
            sw1 += w10 + w11;
            swd0 = fmaf(w00, d00, swd0); swd0 = fmaf(w01, d01, swd0);
            swd1 = fmaf(w10, d10, swd1); swd1 = fmaf(w11, d11, swd1);
            if (d00 < dmin0) { dmin0 = d00; k0 = cb; }
            if (d01 < dmin0) { dmin0 = d01; k0 = cb + 1; }
            if (d10 < dmin1) { dmin1 = d10; k1 = cb; }
            if (d11 < dmin1) { dmin1 = d11; k1 = cb + 1; }
        }

        // quad reduction (4 lanes cover all 256 cols of rows r0, r0+8)
        #pragma unroll
        for (int off = 1; off <= 2; off <<= 1) {
            sw0  += __shfl_xor_sync(0xFFFFFFFFu, sw0,  off);
            swd0 += __shfl_xor_sync(0xFFFFFFFFu, swd0, off);
            sw1  += __shfl_xor_sync(0xFFFFFFFFu, sw1,  off);
            swd1 += __shfl_xor_sync(0xFFFFFFFFu, swd1, off);
            float od0 = __shfl_xor_sync(0xFFFFFFFFu, dmin0, off);
            int   oi0 = __shfl_xor_sync(0xFFFFFFFFu, k0,    off);
            float od1 = __shfl_xor_sync(0xFFFFFFFFu, dmin1, off);
            int   oi1 = __shfl_xor_sync(0xFFFFFFFFu, k1,    off);
            if (od0 < dmin0 || (od0 == dmin0 && oi0 < k0)) { dmin0 = od0; k0 = oi0; }
            if (od1 < dmin1 || (od1 == dmin1 && oi1 < k1)) { dmin1 = od1; k1 = oi1; }
        }

        if (t4 == 0) {
            loss_local += swd0 / sw0 + swd1 / sw1;
            if (k0 < NUM_CLS) {
                int lab = y_is32 ? y32[r0] : y32[2 * r0];
                atomicAdd_block(&s_hist[k0 * NUM_CLS + lab], 1);
            }
            if (k1 < NUM_CLS) {
                int r1 = r0 + 8;
                int lab = y_is32 ? y32[r1] : y32[2 * r1];
                atomicAdd_block(&s_hist[k1 * NUM_CLS + lab], 1);
            }
        }
    }

    // ---- reduce loss: warp shfl -> block double -> global ----
    #pragma unroll
    for (int off = 16; off > 0; off >>= 1)
        loss_local += __shfl_xor_sync(0xFFFFFFFFu, loss_local, off);
    if (lane == 0) atomicAdd_block(&s_loss, (double)loss_local);
    __syncthreads();
    if (tid == 0) atomicAdd(&g_loss, s_loss);
    if (tid < NUM_CLS * NUM_CLS && s_hist[tid] > 0)
        atomicAdd(&g_counts[tid], s_hist[tid]);
}

// ---------------- finalize: greedy label matching ----------------
__global__ void kmeans_finalize_kernel(float* __restrict__ out) {
    if (threadIdx.x != 0 || blockIdx.x != 0) return;

    float counts[NUM_CLS * NUM_CLS];
    #pragma unroll
    for (int i = 0; i < NUM_CLS * NUM_CLS; i++) counts[i] = (float)g_counts[i];

    bool used[NUM_CLS];
    #pragma unroll
    for (int i = 0; i < NUM_CLS; i++) used[i] = false;

    float correct = 0.f;
    for (int i = 0; i < NUM_CLS; i++) {
        const float* bin = &counts[i * NUM_CLS];
        float tot = 0.f;
        for (int j = 0; j < NUM_CLS; j++) tot += bin[j];
        int label = 0; float best = bin[0];
        for (int j = 1; j < NUM_CLS; j++)
            if (bin[j] > best) { best = bin[j]; label = j; }
        if (used[label]) {
            int l2 = 0; float b2 = used[0] ? 0.f : bin[0];
            for (int j = 1; j < NUM_CLS; j++) {
                float v = used[j] ? 0.f : bin[j];
                if (v > b2) { b2 = v; l2 = j; }
            }
            label = l2;
        }
        if (tot > 0.f) { correct += bin[label]; used[label] = true; }
    }
    out[0] = (float)g_loss;
    out[1] = correct / (float)N_ROWS;
}

// ---------------- launch ----------------
extern "C" void kernel_launch(void* const* d_in, const int* in_sizes, int n_in,
                              void* d_out, int out_size) {
    const float* x       = (const float*)d_in[0];
    const int*   y32     = (const int*)d_in[1];
    const float* centers = (const float*)d_in[2];

    const int dyn_smem = (int)sizeof(SmemLayout);   // 64KB B + 1KB c2
    cudaFuncSetAttribute(kmeans_hmma_kernel,
                         cudaFuncAttributeMaxDynamicSharedMemorySize, dyn_smem);

    kmeans_init_kernel<<<1, 128>>>(y32);
    kmeans_hmma_kernel<<<GRID_X, NTHREADS, dyn_smem>>>(x, y32, centers);
    kmeans_finalize_kernel<<<1, 1>>>((float*)d_out);
}

// round 4
// speedup vs baseline: 2.7870x; 1.5872x over previous
#include <cuda_runtime.h>
#include <cuda_bf16.h>
#include <cstdint>
#include <cfloat>

#define N_ROWS   262144
#define K_CENT   256
#define D_DIM    64
#define NUM_CLS  10
#define TILE_M   128
#define N_TILES  (N_ROWS / TILE_M)   /* 2048 */
#define GRID_X   296
#define NTHREADS 256

// ---------------- device-global scratch ----------------
__device__ double g_loss;
__device__ int    g_counts[NUM_CLS * NUM_CLS];
__device__ int    g_y_is32;

// ---------------- helpers ----------------
__device__ __forceinline__ void split2(float a, float b, uint32_t& hi, uint32_t& lo) {
    __nv_bfloat162 h = __floats2bfloat162_rn(a, b);
    float la = a - __bfloat162float(h.x);
    float lb = b - __bfloat162float(h.y);
    __nv_bfloat162 l = __floats2bfloat162_rn(la, lb);
    hi = *reinterpret_cast<uint32_t*>(&h);
    lo = *reinterpret_cast<uint32_t*>(&l);
}

__device__ __forceinline__ void mma_bf16(float& d0, float& d1, float& d2, float& d3,
                                         uint32_t a0, uint32_t a1, uint32_t a2, uint32_t a3,
                                         uint32_t b0, uint32_t b1) {
    asm("mma.sync.aligned.m16n8k16.row.col.f32.bf16.bf16.f32 "
        "{%0,%1,%2,%3}, {%4,%5,%6,%7}, {%8,%9}, {%0,%1,%2,%3};"
        : "+f"(d0), "+f"(d1), "+f"(d2), "+f"(d3)
        : "r"(a0), "r"(a1), "r"(a2), "r"(a3), "r"(b0), "r"(b1));
}

// argmin key: truncate e mantissa low bits, pack col into low byte (ties -> lower col)
__device__ __forceinline__ uint32_t akey(float e, int col) {
    return (__float_as_uint(e) & 0xFFFFFF00u) | (uint32_t)col;
}

// ---------------- init: zero accumulators + detect label dtype ----------------
__global__ void kmeans_init_kernel(const int* __restrict__ y32) {
    int t = threadIdx.x;
    if (t < NUM_CLS * NUM_CLS) g_counts[t] = 0;
    if (t == 0) { g_loss = 0.0; g_y_is32 = 0; }
    __syncthreads();
    if (t < 128) {
        if (y32[2 * t + 1] != 0) atomicOr(&g_y_is32, 1);
    }
}

struct SmemLayout {
    uint4 B[K_CENT * 16];   // (n, unit): {hi_b0, hi_b1, lo_b0, lo_b1}, XOR-swizzled
    float c2[K_CENT];       // holds c2[n] + 1  (the "+1" of 1+d folded in)
};

__global__ __launch_bounds__(NTHREADS, 2)
void kmeans_hmma_kernel(const float* __restrict__ x,
                        const int*   __restrict__ y32,
                        const float* __restrict__ centers) {
    extern __shared__ unsigned char s_raw[];
    SmemLayout* sm = reinterpret_cast<SmemLayout*>(s_raw);
    __shared__ int    s_hist[NUM_CLS * NUM_CLS];
    __shared__ double s_loss;

    const int tid  = threadIdx.x;
    const int wid  = tid >> 5;
    const int lane = tid & 31;
    const int g    = lane >> 2;   // row group within mma tile (0..7)
    const int t4   = lane & 3;

    if (tid < NUM_CLS * NUM_CLS) s_hist[tid] = 0;
    if (tid == 0) s_loss = 0.0;

    // ---- build B fragments (centers hi/lo) in smem, once per CTA ----
    for (int w = tid; w < K_CENT * 16; w += NTHREADS) {
        int n   = w >> 4;
        int u16 = w & 15;
        int kc = u16 >> 2, tt = u16 & 3;
        int kb = kc * 16 + tt * 2;
        const float* cn = centers + n * D_DIM;
        float2 pa = *(const float2*)(cn + kb);
        float2 pb = *(const float2*)(cn + kb + 8);
        uint32_t hi0, lo0, hi1, lo1;
        split2(pa.x, pa.y, hi0, lo0);
        split2(pb.x, pb.y, hi1, lo1);
        int u = u16 ^ ((n & 1) << 2);
        sm->B[n * 16 + u] = make_uint4(hi0, hi1, lo0, lo1);
    }
    // center norms + 1 (fp32 exact)
    if (tid < K_CENT) {
        const float4* cp = (const float4*)(centers + tid * D_DIM);
        float a = 0.f;
        #pragma unroll
        for (int j = 0; j < 16; j++) {
            float4 v = cp[j];
            a = fmaf(v.x, v.x, a); a = fmaf(v.y, v.y, a);
            a = fmaf(v.z, v.z, a); a = fmaf(v.w, v.w, a);
        }
        sm->c2[tid] = a + 1.0f;
    }
    __syncthreads();
    const int y_is32 = g_y_is32;

    const uint4* Bbase = sm->B + g * 16;
    const int    uswz  = (g & 1) << 2;

    float loss_local = 0.f;

    for (int t = blockIdx.x; t < N_TILES; t += GRID_X) {
        const int r0 = t * TILE_M + wid * 16 + g;   // rows r0, r0+8
        const float* xr0 = x + (size_t)r0 * D_DIM;
        const float* xr1 = xr0 + 8 * D_DIM;

        // ---- A fragments (hi/lo) + row-norm partials ----
        uint32_t ahi[4][4], alo[4][4];
        float x2a = 0.f, x2b = 0.f;
        #pragma unroll
        for (int kc = 0; kc < 4; kc++) {
            int cb = kc * 16 + t4 * 2;
            float2 p00 = *(const float2*)(xr0 + cb);
            float2 p01 = *(const float2*)(xr0 + cb + 8);
            float2 p10 = *(const float2*)(xr1 + cb);
            float2 p11 = *(const float2*)(xr1 + cb + 8);
            x2a = fmaf(p00.x, p00.x, x2a); x2a = fmaf(p00.y, p00.y, x2a);
            x2a = fmaf(p01.x, p01.x, x2a); x2a = fmaf(p01.y, p01.y, x2a);
            x2b = fmaf(p10.x, p10.x, x2b); x2b = fmaf(p10.y, p10.y, x2b);
            x2b = fmaf(p11.x, p11.x, x2b); x2b = fmaf(p11.y, p11.y, x2b);
            split2(p00.x, p00.y, ahi[kc][0], alo[kc][0]);
            split2(p10.x, p10.y, ahi[kc][1], alo[kc][1]);
            split2(p01.x, p01.y, ahi[kc][2], alo[kc][2]);
            split2(p11.x, p11.y, ahi[kc][3], alo[kc][3]);
        }
        x2a += __shfl_xor_sync(0xFFFFFFFFu, x2a, 1);
        x2a += __shfl_xor_sync(0xFFFFFFFFu, x2a, 2);
        x2b += __shfl_xor_sync(0xFFFFFFFFu, x2b, 1);
        x2b += __shfl_xor_sync(0xFFFFFFFFu, x2b, 2);

        float sw0 = 0.f, swe0 = 0.f, sw1 = 0.f, swe1 = 0.f;
        uint32_t best0 = 0xFFFFFFFFu, best1 = 0xFFFFFFFFu;

        #pragma unroll 2
        for (int ng = 0; ng < 32; ng++) {
            float2 c2p = *(const float2*)(sm->c2 + ng * 8 + t4 * 2);
            // two INDEPENDENT accumulation chains: hi-terms (8 mma), lo-terms (4 mma)
            float h0 = 0.f, h1 = 0.f, h2 = 0.f, h3 = 0.f;
            float l0 = 0.f, l1 = 0.f, l2 = 0.f, l3 = 0.f;
            const uint4* Bn = Bbase + ng * 128;
            #pragma unroll
            for (int kc = 0; kc < 4; kc++) {
                uint4 bv = Bn[(kc * 4 + t4) ^ uswz];
                mma_bf16(h0, h1, h2, h3,
                         ahi[kc][0], ahi[kc][1], ahi[kc][2], ahi[kc][3], bv.x, bv.y);
                mma_bf16(l0, l1, l2, l3,
                         alo[kc][0], alo[kc][1], alo[kc][2], alo[kc][3], bv.x, bv.y);
                mma_bf16(h0, h1, h2, h3,
                         ahi[kc][0], ahi[kc][1], ahi[kc][2], ahi[kc][3], bv.z, bv.w);
            }
            // e = 1 + d = (x2 + c2 + 1) - 2*(accH + accL)
            const int cb = ng * 8 + t4 * 2;
            float e00 = fmaf(-2.f, h0, fmaf(-2.f, l0, x2a + c2p.x));
            float e01 = fmaf(-2.f, h1, fmaf(-2.f, l1, x2a + c2p.y));
            float e10 = fmaf(-2.f, h2, fmaf(-2.f, l2, x2b + c2p.x));
            float e11 = fmaf(-2.f, h3, fmaf(-2.f, l3, x2b + c2p.y));
            float w00 = __powf(e00, -0.1f);
            float w01 = __powf(e01, -0.1f);
            float w10 = __powf(e10, -0.1f);
            float w11 = __powf(e11, -0.1f);
            sw0 += w00 + w01;
            sw1 += w10 + w11;
            swe0 = fmaf(w00, e00, swe0); swe0 = fmaf(w01, e01, swe0);
            swe1 = fmaf(w10, e10, swe1); swe1 = fmaf(w11, e11, swe1);
            best0 = min(best0, min(akey(e00, cb), akey(e01, cb + 1)));
            best1 = min(best1, min(akey(e10, cb), akey(e11, cb + 1)));
        }

        // quad reduction (4 lanes cover all 256 cols of rows r0, r0+8)
        #pragma unroll
        for (int off = 1; off <= 2; off <<= 1) {
            sw0  += __shfl_xor_sync(0xFFFFFFFFu, sw0,  off);
            swe0 += __shfl_xor_sync(0xFFFFFFFFu, swe0, off);
            sw1  += __shfl_xor_sync(0xFFFFFFFFu, sw1,  off);
            swe1 += __shfl_xor_sync(0xFFFFFFFFu, swe1, off);
            best0 = min(best0, __shfl_xor_sync(0xFFFFFFFFu, best0, off));
            best1 = min(best1, __shfl_xor_sync(0xFFFFFFFFu, best1, off));
        }

        if (t4 == 0) {
            // sum_w*d / sum_w = (sum_w*e - sum_w)/sum_w = swe/sw - 1
            loss_local += swe0 / sw0 + swe1 / sw1 - 2.0f;
            int k0 = (int)(best0 & 0xFFu);
            int k1 = (int)(best1 & 0xFFu);
            if (k0 < NUM_CLS) {
                int lab = y_is32 ? y32[r0] : y32[2 * r0];
                atomicAdd_block(&s_hist[k0 * NUM_CLS + lab], 1);
            }
            if (k1 < NUM_CLS) {
                int r1 = r0 + 8;
                int lab = y_is32 ? y32[r1] : y32[2 * r1];
                atomicAdd_block(&s_hist[k1 * NUM_CLS + lab], 1);
            }
        }
    }

    // ---- reduce loss ----
    #pragma unroll
    for (int off = 16; off > 0; off >>= 1)
        loss_local += __shfl_xor_sync(0xFFFFFFFFu, loss_local, off);
    if (lane == 0) atomicAdd_block(&s_loss, (double)loss_local);
    __syncthreads();
    if (tid == 0) atomicAdd(&g_loss, s_loss);
    if (tid < NUM_CLS * NUM_CLS && s_hist[tid] > 0)
        atomicAdd(&g_counts[tid], s_hist[tid]);
}

// ---------------- finalize: greedy label matching ----------------
__global__ void kmeans_finalize_kernel(float* __restrict__ out) {
    if (threadIdx.x != 0 || blockIdx.x != 0) return;

    float counts[NUM_CLS * NUM_CLS];
    #pragma unroll
    for (int i = 0; i < NUM_CLS * NUM_CLS; i++) counts[i] = (float)g_counts[i];

    bool used[NUM_CLS];
    #pragma unroll
    for (int i = 0; i < NUM_CLS; i++) used[i] = false;

    float correct = 0.f;
    for (int i = 0; i < NUM_CLS; i++) {
        const float* bin = &counts[i * NUM_CLS];
        float tot = 0.f;
        for (int j = 0; j < NUM_CLS; j++) tot += bin[j];
        int label = 0; float best = bin[0];
        for (int j = 1; j < NUM_CLS; j++)
            if (bin[j] > best) { best = bin[j]; label = j; }
        if (used[label]) {
            int l2 = 0; float b2 = used[0] ? 0.f : bin[0];
            for (int j = 1; j < NUM_CLS; j++) {
                float v = used[j] ? 0.f : bin[j];
                if (v > b2) { b2 = v; l2 = j; }
            }
            label = l2;
        }
        if (tot > 0.f) { correct += bin[label]; used[label] = true; }
    }
    out[0] = (float)g_loss;
    out[1] = correct / (float)N_ROWS;
}

// ---------------- launch ----------------
extern "C" void kernel_launch(void* const* d_in, const int* in_sizes, int n_in,
                              void* d_out, int out_size) {
    const float* x       = (const float*)d_in[0];
    const int*   y32     = (const int*)d_in[1];
    const float* centers = (const float*)d_in[2];

    const int dyn_smem = (int)sizeof(SmemLayout);
    cudaFuncSetAttribute(kmeans_hmma_kernel,
                         cudaFuncAttributeMaxDynamicSharedMemorySize, dyn_smem);

    kmeans_init_kernel<<<1, 128>>>(y32);
    kmeans_hmma_kernel<<<GRID_X, NTHREADS, dyn_smem>>>(x, y32, centers);
    kmeans_finalize_kernel<<<1, 1>>>((float*)d_out);
}

// round 5
// speedup vs baseline: 4.1607x; 1.4929x over previous
#include <cuda_runtime.h>
#include <cuda_fp16.h>
#include <cstdint>
#include <cfloat>

#define N_ROWS   262144
#define K_CENT   256
#define D_DIM    64
#define NUM_CLS  10
#define TILE_M   128
#define N_TILES  (N_ROWS / TILE_M)   /* 2048 */
#define GRID_X   296
#define NTHREADS 256

// ---------------- device-global scratch ----------------
__device__ double g_loss;
__device__ int    g_counts[NUM_CLS * NUM_CLS];
__device__ int    g_y_is32;

// ---------------- helpers ----------------
__device__ __forceinline__ uint32_t h2(float a, float b) {
    __half2 h = __floats2half2_rn(a, b);
    return *reinterpret_cast<uint32_t*>(&h);
}

// mma.sync m16n8k16 fp16 -> f32 accumulate
__device__ __forceinline__ void mma_f16(float& d0, float& d1, float& d2, float& d3,
                                        uint32_t a0, uint32_t a1, uint32_t a2, uint32_t a3,
                                        uint32_t b0, uint32_t b1) {
    asm("mma.sync.aligned.m16n8k16.row.col.f32.f16.f16.f32 "
        "{%0,%1,%2,%3}, {%4,%5,%6,%7}, {%8,%9}, {%0,%1,%2,%3};"
        : "+f"(d0), "+f"(d1), "+f"(d2), "+f"(d3)
        : "r"(a0), "r"(a1), "r"(a2), "r"(a3), "r"(b0), "r"(b1));
}

// argmin key: truncate e mantissa low bits, pack col into low byte (ties -> lower col)
__device__ __forceinline__ uint32_t akey(float e, int col) {
    return (__float_as_uint(e) & 0xFFFFFF00u) | (uint32_t)col;
}

// ---------------- init: zero accumulators + detect label dtype ----------------
__global__ void kmeans_init_kernel(const int* __restrict__ y32) {
    int t = threadIdx.x;
    if (t < NUM_CLS * NUM_CLS) g_counts[t] = 0;
    if (t == 0) { g_loss = 0.0; g_y_is32 = 0; }
    __syncthreads();
    if (t < 128) {
        if (y32[2 * t + 1] != 0) atomicOr(&g_y_is32, 1);
    }
}

// smem: per center n, 8 uint4 units. unit u=(kcp*4+t4)^((n&1)<<2) holds
// {b0,b1} fragments for k-chunks 2*kcp and 2*kcp+1. Conflict-free LDS.128.
struct SmemLayout {
    uint4 B[K_CENT * 8];    // 32 KB
    float c2[K_CENT];       // c2[n] + 1  (the "+1" of 1+d folded in)
};

__global__ __launch_bounds__(NTHREADS, 2)
void kmeans_hmma_kernel(const float* __restrict__ x,
                        const int*   __restrict__ y32,
                        const float* __restrict__ centers) {
    extern __shared__ unsigned char s_raw[];
    SmemLayout* sm = reinterpret_cast<SmemLayout*>(s_raw);
    __shared__ int    s_hist[NUM_CLS * NUM_CLS];
    __shared__ double s_loss;

    const int tid  = threadIdx.x;
    const int wid  = tid >> 5;
    const int lane = tid & 31;
    const int g    = lane >> 2;   // row within mma row-group (0..7)
    const int t4   = lane & 3;

    if (tid < NUM_CLS * NUM_CLS) s_hist[tid] = 0;
    if (tid == 0) s_loss = 0.0;

    // ---- build fp16 B fragments in smem, once per CTA ----
    for (int w = tid; w < K_CENT * 8; w += NTHREADS) {
        int n   = w >> 3;
        int u8  = w & 7;
        int kcp = u8 >> 2, tt = u8 & 3;
        const float* cn = centers + n * D_DIM;
        int kb0 = (2 * kcp) * 16 + tt * 2;   // k-chunk 2*kcp
        int kb1 = kb0 + 16;                  // k-chunk 2*kcp+1
        float2 p00 = *(const float2*)(cn + kb0);
        float2 p01 = *(const float2*)(cn + kb0 + 8);
        float2 p10 = *(const float2*)(cn + kb1);
        float2 p11 = *(const float2*)(cn + kb1 + 8);
        int u = u8 ^ ((n & 1) << 2);
        sm->B[n * 8 + u] = make_uint4(h2(p00.x, p00.y), h2(p01.x, p01.y),
                                      h2(p10.x, p10.y), h2(p11.x, p11.y));
    }
    // center norms + 1 (fp32 exact)
    if (tid < K_CENT) {
        const float4* cp = (const float4*)(centers + tid * D_DIM);
        float a = 0.f;
        #pragma unroll
        for (int j = 0; j < 16; j++) {
            float4 v = cp[j];
            a = fmaf(v.x, v.x, a); a = fmaf(v.y, v.y, a);
            a = fmaf(v.z, v.z, a); a = fmaf(v.w, v.w, a);
        }
        sm->c2[tid] = a + 1.0f;
    }
    __syncthreads();
    const int y_is32 = g_y_is32;

    const uint4* Bbase = sm->B + g * 8;
    const int    uswz  = (g & 1) << 2;

    float loss_local = 0.f;

    for (int t = blockIdx.x; t < N_TILES; t += GRID_X) {
        const int r0 = t * TILE_M + wid * 16 + g;   // rows r0, r0+8
        const float* xr0 = x + (size_t)r0 * D_DIM;
        const float* xr1 = xr0 + 8 * D_DIM;

        // ---- fp16 A fragments + row-norm partials ----
        uint32_t ah[4][4];
        float x2a = 0.f, x2b = 0.f;
        #pragma unroll
        for (int kc = 0; kc < 4; kc++) {
            int cb = kc * 16 + t4 * 2;
            float2 p00 = *(const float2*)(xr0 + cb);
            float2 p01 = *(const float2*)(xr0 + cb + 8);
            float2 p10 = *(const float2*)(xr1 + cb);
            float2 p11 = *(const float2*)(xr1 + cb + 8);
            x2a = fmaf(p00.x, p00.x, x2a); x2a = fmaf(p00.y, p00.y, x2a);
            x2a = fmaf(p01.x, p01.x, x2a); x2a = fmaf(p01.y, p01.y, x2a);
            x2b = fmaf(p10.x, p10.x, x2b); x2b = fmaf(p10.y, p10.y, x2b);
            x2b = fmaf(p11.x, p11.x, x2b); x2b = fmaf(p11.y, p11.y, x2b);
            ah[kc][0] = h2(p00.x, p00.y);
            ah[kc][1] = h2(p10.x, p10.y);
            ah[kc][2] = h2(p01.x, p01.y);
            ah[kc][3] = h2(p11.x, p11.y);
        }
        x2a += __shfl_xor_sync(0xFFFFFFFFu, x2a, 1);
        x2a += __shfl_xor_sync(0xFFFFFFFFu, x2a, 2);
        x2b += __shfl_xor_sync(0xFFFFFFFFu, x2b, 1);
        x2b += __shfl_xor_sync(0xFFFFFFFFu, x2b, 2);

        float sw0 = 0.f, swe0 = 0.f, sw1 = 0.f, swe1 = 0.f;
        uint32_t best0 = 0xFFFFFFFFu, best1 = 0xFFFFFFFFu;

        #pragma unroll 4
        for (int ng = 0; ng < 32; ng++) {
            float2 c2p = *(const float2*)(sm->c2 + ng * 8 + t4 * 2);
            float a0 = 0.f, a1 = 0.f, a2 = 0.f, a3 = 0.f;
            const uint4* Bn = Bbase + ng * 64;   // +ng*8 centers * 8 units
            uint4 bv0 = Bn[(0 + t4) ^ uswz];     // k-chunks 0,1
            uint4 bv1 = Bn[(4 + t4) ^ uswz];     // k-chunks 2,3
            mma_f16(a0, a1, a2, a3, ah[0][0], ah[0][1], ah[0][2], ah[0][3], bv0.x, bv0.y);
            mma_f16(a0, a1, a2, a3, ah[1][0], ah[1][1], ah[1][2], ah[1][3], bv0.z, bv0.w);
            mma_f16(a0, a1, a2, a3, ah[2][0], ah[2][1], ah[2][2], ah[2][3], bv1.x, bv1.y);
            mma_f16(a0, a1, a2, a3, ah[3][0], ah[3][1], ah[3][2], ah[3][3], bv1.z, bv1.w);

            // e = 1 + d = (x2 + c2 + 1) - 2*dot
            const int cb = ng * 8 + t4 * 2;
            float e00 = fmaf(-2.f, a0, x2a + c2p.x);
            float e01 = fmaf(-2.f, a1, x2a + c2p.y);
            float e10 = fmaf(-2.f, a2, x2b + c2p.x);
            float e11 = fmaf(-2.f, a3, x2b + c2p.y);
            float w00 = __powf(e00, -0.1f);
            float w01 = __powf(e01, -0.1f);
            float w10 = __powf(e10, -0.1f);
            float w11 = __powf(e11, -0.1f);
            sw0 += w00 + w01;
            sw1 += w10 + w11;
            swe0 = fmaf(w00, e00, swe0); swe0 = fmaf(w01, e01, swe0);
            swe1 = fmaf(w10, e10, swe1); swe1 = fmaf(w11, e11, swe1);
            best0 = min(best0, min(akey(e00, cb), akey(e01, cb + 1)));
            best1 = min(best1, min(akey(e10, cb), akey(e11, cb + 1)));
        }

        // quad reduction (4 lanes cover all 256 cols of rows r0, r0+8)
        #pragma unroll
        for (int off = 1; off <= 2; off <<= 1) {
            sw0  += __shfl_xor_sync(0xFFFFFFFFu, sw0,  off);
            swe0 += __shfl_xor_sync(0xFFFFFFFFu, swe0, off);
            sw1  += __shfl_xor_sync(0xFFFFFFFFu, sw1,  off);
            swe1 += __shfl_xor_sync(0xFFFFFFFFu, swe1, off);
            best0 = min(best0, __shfl_xor_sync(0xFFFFFFFFu, best0, off));
            best1 = min(best1, __shfl_xor_sync(0xFFFFFFFFu, best1, off));
        }

        if (t4 == 0) {
            // sum_w*d/sum_w = swe/sw - 1
            loss_local += swe0 / sw0 + swe1 / sw1 - 2.0f;
            int k0 = (int)(best0 & 0xFFu);
            int k1 = (int)(best1 & 0xFFu);
            if (k0 < NUM_CLS) {
                int lab = y_is32 ? y32[r0] : y32[2 * r0];
                atomicAdd_block(&s_hist[k0 * NUM_CLS + lab], 1);
            }
            if (k1 < NUM_CLS) {
                int r1 = r0 + 8;
                int lab = y_is32 ? y32[r1] : y32[2 * r1];
                atomicAdd_block(&s_hist[k1 * NUM_CLS + lab], 1);
            }
        }
    }

    // ---- reduce loss ----
    #pragma unroll
    for (int off = 16; off > 0; off >>= 1)
        loss_local += __shfl_xor_sync(0xFFFFFFFFu, loss_local, off);
    if (lane == 0) atomicAdd_block(&s_loss, (double)loss_local);
    __syncthreads();
    if (tid == 0) atomicAdd(&g_loss, s_loss);
    if (tid < NUM_CLS * NUM_CLS && s_hist[tid] > 0)
        atomicAdd(&g_counts[tid], s_hist[tid]);
}

// ---------------- finalize: greedy label matching ----------------
__global__ void kmeans_finalize_kernel(float* __restrict__ out) {
    if (threadIdx.x != 0 || blockIdx.x != 0) return;

    float counts[NUM_CLS * NUM_CLS];
    #pragma unroll
    for (int i = 0; i < NUM_CLS * NUM_CLS; i++) counts[i] = (float)g_counts[i];

    bool used[NUM_CLS];
    #pragma unroll
    for (int i = 0; i < NUM_CLS; i++) used[i] = false;

    float correct = 0.f;
    for (int i = 0; i < NUM_CLS; i++) {
        const float* bin = &counts[i * NUM_CLS];
        float tot = 0.f;
        for (int j = 0; j < NUM_CLS; j++) tot += bin[j];
        int label = 0; float best = bin[0];
        for (int j = 1; j < NUM_CLS; j++)
            if (bin[j] > best) { best = bin[j]; label = j; }
        if (used[label]) {
            int l2 = 0; float b2 = used[0] ? 0.f : bin[0];
            for (int j = 1; j < NUM_CLS; j++) {
                float v = used[j] ? 0.f : bin[j];
                if (v > b2) { b2 = v; l2 = j; }
            }
            label = l2;
        }
        if (tot > 0.f) { correct += bin[label]; used[label] = true; }
    }
    out[0] = (float)g_loss;
    out[1] = correct / (float)N_ROWS;
}

// ---------------- launch ----------------
extern "C" void kernel_launch(void* const* d_in, const int* in_sizes, int n_in,
                              void* d_out, int out_size) {
    const float* x       = (const float*)d_in[0];
    const int*   y32     = (const int*)d_in[1];
    const float* centers = (const float*)d_in[2];

    const int dyn_smem = (int)sizeof(SmemLayout);
    cudaFuncSetAttribute(kmeans_hmma_kernel,
                         cudaFuncAttributeMaxDynamicSharedMemorySize, dyn_smem);

    kmeans_init_kernel<<<1, 128>>>(y32);
    kmeans_hmma_kernel<<<GRID_X, NTHREADS, dyn_smem>>>(x, y32, centers);
    kmeans_finalize_kernel<<<1, 1>>>((float*)d_out);
}